// round 16
// baseline (speedup 1.0000x reference)
#include <cuda_runtime.h>
#include <cstdint>
#include <cstddef>

#define BB    8
#define CIN   128
#define CO    128
#define LIN   2048
#define LOUT  4096
#define CCAT  512
#define DM    256
#define NST   32
#define SST   136   // smem row stride (floats): conflict-free

// ---------------- device scratch (static: allocation-free) ----------------
__device__ float g_xh[(size_t)BB * CIN * LIN];    // tf32-split input x
__device__ float g_xl[(size_t)BB * CIN * LIN];
__device__ float g_wkh[8 * 128 * 128];            // packed deconv weights (tf32 hi)
__device__ float g_aeh[(size_t)BB * CCAT * LIN];  // split even-position activations
__device__ float g_ael[(size_t)BB * CCAT * LIN];
__device__ float g_aoh[(size_t)BB * CO * LIN];    // split odd-position (branch-1 tap1)
__device__ float g_aol[(size_t)BB * CO * LIN];
__device__ float g_part[5 * BB * 16 * 128 * 2];   // per-block stats partials
__device__ float g_scale[CCAT];
__device__ float g_shift[CCAT];
__device__ float g_GwTh[CCAT * DM];               // folded 1x1 weights [c][m] (tf32 hi)
__device__ float g_Gb[DM];
__device__ float g_Gbodd[DM];
__device__ float g_ue[(size_t)BB * DM * LIN];
__device__ float g_uo[(size_t)BB * DM * LIN];
__device__ float g_ssm[4 * DM * NST];             // a1, a2, b0, b1 (2nd-order real IIR)

// ---------------- tf32 helpers ----------------
__device__ __forceinline__ uint32_t cvt_tf32(float x) {
    uint32_t r;
    asm("cvt.rna.tf32.f32 %0, %1;" : "=r"(r) : "f"(x));
    return r;
}
__device__ __forceinline__ void mma8(float* d, const uint32_t* a, uint32_t b0, uint32_t b1) {
    asm("mma.sync.aligned.m16n8k8.row.col.f32.tf32.tf32.f32 "
        "{%0,%1,%2,%3}, {%4,%5,%6,%7}, {%8,%9}, {%0,%1,%2,%3};"
        : "+f"(d[0]), "+f"(d[1]), "+f"(d[2]), "+f"(d[3])
        : "r"(a[0]), "r"(a[1]), "r"(a[2]), "r"(a[3]), "r"(b0), "r"(b1));
}
__device__ __forceinline__ float2 upk2(unsigned long long v) {
    float2 f;
    asm("mov.b64 {%0, %1}, %2;" : "=f"(f.x), "=f"(f.y) : "l"(v));
    return f;
}
__device__ __forceinline__ unsigned long long pk2(float lo, float hi) {
    unsigned long long r;
    asm("mov.b64 %0, {%1, %2};" : "=l"(r) : "f"(lo), "f"(hi));
    return r;
}
__device__ __forceinline__ unsigned long long fma2d(unsigned long long a, unsigned long long b,
                                                    unsigned long long c) {
    unsigned long long d;
    asm("fma.rn.f32x2 %0, %1, %2, %3;" : "=l"(d) : "l"(a), "l"(b), "l"(c));
    return d;
}
__device__ __forceinline__ unsigned long long mul2d(unsigned long long a, unsigned long long b) {
    unsigned long long d;
    asm("mul.rn.f32x2 %0, %1, %2;" : "=l"(d) : "l"(a), "l"(b));
    return d;
}

// ---------------- cp.async helpers ----------------
__device__ __forceinline__ void cpa16(void* dst, const void* src) {
    unsigned ds = (unsigned)__cvta_generic_to_shared(dst);
    asm volatile("cp.async.cg.shared.global [%0], [%1], 16;" :: "r"(ds), "l"(src));
}
__device__ __forceinline__ void cpa_commit() { asm volatile("cp.async.commit_group;"); }
__device__ __forceinline__ void cpa_wait1()  { asm volatile("cp.async.wait_group 1;"); }

// ---------------- K_w: pack deconv weights (tf32 hi only) ----------------
// plane: 0=w1t0 1=w2t0 2=w2t1 3=w3t0 4=w3t1 5=w4t0 6=w4t1 7=w1t1
__global__ void k_wprep(const float* __restrict__ w1, const float* __restrict__ w2,
                        const float* __restrict__ w3, const float* __restrict__ w4)
{
    int idx = blockIdx.x * 256 + threadIdx.x;
    int plane = idx >> 14;
    int r = idx & 16383;
    const float* w; int tap;
    switch (plane) {
        case 0: w = w1; tap = 0; break;
        case 1: w = w2; tap = 0; break;
        case 2: w = w2; tap = 1; break;
        case 3: w = w3; tap = 0; break;
        case 4: w = w3; tap = 1; break;
        case 5: w = w4; tap = 0; break;
        case 6: w = w4; tap = 1; break;
        default: w = w1; tap = 1; break;
    }
    g_wkh[idx] = __uint_as_float(cvt_tf32(w[r * 2 + tap]));
}

// ---------------- K_x: split input x ----------------
__global__ void k_xprep(const float* __restrict__ x)
{
    size_t i = ((size_t)blockIdx.x * 256 + threadIdx.x) * 4;
    float4 v = *(const float4*)&x[i];
    float4 h, l;
    uint32_t t;
    t = cvt_tf32(v.x); h.x = __uint_as_float(t); l.x = __uint_as_float(cvt_tf32(v.x - h.x));
    t = cvt_tf32(v.y); h.y = __uint_as_float(t); l.y = __uint_as_float(cvt_tf32(v.y - h.y));
    t = cvt_tf32(v.z); h.z = __uint_as_float(t); l.z = __uint_as_float(cvt_tf32(v.z - h.z));
    t = cvt_tf32(v.w); h.w = __uint_as_float(t); l.w = __uint_as_float(cvt_tf32(v.w - h.w));
    *(float4*)&g_xh[i] = h;
    *(float4*)&g_xl[i] = l;
}

// ---------------- K1: fused deconv GEMMs (2-stage, K-chunk = 16 channels) ----------------
__global__ void __launch_bounds__(256) k1_deconv(
    const float* __restrict__ b1, const float* __restrict__ b2,
    const float* __restrict__ b3, const float* __restrict__ b4)
{
    extern __shared__ float dsm[];
    float* XH  = dsm;               // [2][16][SST]
    float* XL  = XH  + 2 * 16 * SST;
    float* W0H = XL  + 2 * 16 * SST;
    float* W1H = W0H + 2 * 16 * SST;
    __shared__ float spart[2][128][2];

    const int tid = threadIdx.x;
    const int b   = blockIdx.z;
    const int seg = blockIdx.y;
    const int l0  = blockIdx.x * 128;
    const int lane = tid & 31, wid = tid >> 5;
    const int tg = lane & 3, gid = lane >> 2;
    const int wm = wid & 3, wn = wid >> 2;
    const int mb = wm * 32, nb = wn * 64;

    int p0, p1, dj, cbase; bool act, toAo;
    const float* bp;
    switch (seg) {
        case 0:  p0 = 0; p1 = -1; dj = 0; act = false; toAo = false; cbase = 0;   bp = b1; break;
        case 1:  p0 = 1; p1 = 2;  dj = 1; act = true;  toAo = false; cbase = 128; bp = b2; break;
        case 2:  p0 = 3; p1 = 4;  dj = 2; act = true;  toAo = false; cbase = 256; bp = b3; break;
        case 3:  p0 = 5; p1 = 6;  dj = 4; act = true;  toAo = false; cbase = 384; bp = b4; break;
        default: p0 = 7; p1 = -1; dj = 0; act = false; toAo = true;  cbase = 0;   bp = b1; break;
    }
    const bool dual = (p1 >= 0);

    float acc[2][8][4];
#pragma unroll
    for (int mt = 0; mt < 2; ++mt)
#pragma unroll
        for (int n8 = 0; n8 < 8; ++n8)
#pragma unroll
            for (int q = 0; q < 4; ++q) acc[mt][n8][q] = 0.f;

    auto issue = [&](int ch) {
        const int buf = ch & 1;
        const int c0  = ch * 16;
        for (int e = tid; e < 528; e += 256) {
            int row = e / 33;
            int q   = e - row * 33;
            int off = (buf * 16 + row) * SST + q * 4;
            if (l0 == 0 && q == 0) {
                *(float4*)&XH[off] = make_float4(0.f, 0.f, 0.f, 0.f);
                *(float4*)&XL[off] = make_float4(0.f, 0.f, 0.f, 0.f);
            } else {
                size_t src = (size_t)(b * 128 + c0 + row) * LIN + l0 - 4 + q * 4;
                cpa16(&XH[off], &g_xh[src]);
                cpa16(&XL[off], &g_xl[src]);
            }
        }
#pragma unroll
        for (int r = 0; r < 2; ++r) {
            int e = tid + r * 256;
            int row = e >> 5, q = e & 31;
            int woff = (buf * 16 + row) * SST + q * 4;
            size_t ws0 = (size_t)p0 * 16384 + (c0 + row) * 128 + q * 4;
            cpa16(&W0H[woff], &g_wkh[ws0]);
            if (dual) {
                size_t ws1 = (size_t)p1 * 16384 + (c0 + row) * 128 + q * 4;
                cpa16(&W1H[woff], &g_wkh[ws1]);
            }
        }
    };

    issue(0); cpa_commit();
    const int NCH = 8;
    for (int ch = 0; ch < NCH; ++ch) {
        if (ch + 1 < NCH) issue(ch + 1);
        cpa_commit();
        cpa_wait1();
        __syncthreads();
        const int bo = (ch & 1) * 16 * SST;

#pragma unroll
        for (int kk = 0; kk < 16; kk += 8) {
            uint32_t bh[8][2], bl[8][2];
#pragma unroll
            for (int n8 = 0; n8 < 8; ++n8) {
                int c = 4 + nb + n8 * 8 + gid;
                bh[n8][0] = __float_as_uint(XH[bo + (kk + tg) * SST + c]);
                bh[n8][1] = __float_as_uint(XH[bo + (kk + tg + 4) * SST + c]);
                bl[n8][0] = __float_as_uint(XL[bo + (kk + tg) * SST + c]);
                bl[n8][1] = __float_as_uint(XL[bo + (kk + tg + 4) * SST + c]);
            }
            uint32_t ah[2][4];
#pragma unroll
            for (int mt = 0; mt < 2; ++mt) {
                int mr = mb + mt * 16;
                ah[mt][0] = __float_as_uint(W0H[bo + (kk + tg) * SST + mr + gid]);
                ah[mt][1] = __float_as_uint(W0H[bo + (kk + tg) * SST + mr + gid + 8]);
                ah[mt][2] = __float_as_uint(W0H[bo + (kk + tg + 4) * SST + mr + gid]);
                ah[mt][3] = __float_as_uint(W0H[bo + (kk + tg + 4) * SST + mr + gid + 8]);
            }
#pragma unroll
            for (int n8 = 0; n8 < 8; ++n8)
#pragma unroll
                for (int mt = 0; mt < 2; ++mt)
                    mma8(acc[mt][n8], ah[mt], bh[n8][0], bh[n8][1]);
#pragma unroll
            for (int n8 = 0; n8 < 8; ++n8)
#pragma unroll
                for (int mt = 0; mt < 2; ++mt)
                    mma8(acc[mt][n8], ah[mt], bl[n8][0], bl[n8][1]);

            if (dual) {
                const int off = 4 - dj;
#pragma unroll
                for (int n8 = 0; n8 < 8; ++n8) {
                    int c = off + nb + n8 * 8 + gid;
                    bh[n8][0] = __float_as_uint(XH[bo + (kk + tg) * SST + c]);
                    bh[n8][1] = __float_as_uint(XH[bo + (kk + tg + 4) * SST + c]);
                    bl[n8][0] = __float_as_uint(XL[bo + (kk + tg) * SST + c]);
                    bl[n8][1] = __float_as_uint(XL[bo + (kk + tg + 4) * SST + c]);
                }
#pragma unroll
                for (int mt = 0; mt < 2; ++mt) {
                    int mr = mb + mt * 16;
                    ah[mt][0] = __float_as_uint(W1H[bo + (kk + tg) * SST + mr + gid]);
                    ah[mt][1] = __float_as_uint(W1H[bo + (kk + tg) * SST + mr + gid + 8]);
                    ah[mt][2] = __float_as_uint(W1H[bo + (kk + tg + 4) * SST + mr + gid]);
                    ah[mt][3] = __float_as_uint(W1H[bo + (kk + tg + 4) * SST + mr + gid + 8]);
                }
#pragma unroll
                for (int n8 = 0; n8 < 8; ++n8)
#pragma unroll
                    for (int mt = 0; mt < 2; ++mt)
                        mma8(acc[mt][n8], ah[mt], bh[n8][0], bh[n8][1]);
#pragma unroll
                for (int n8 = 0; n8 < 8; ++n8)
#pragma unroll
                    for (int mt = 0; mt < 2; ++mt)
                        mma8(acc[mt][n8], ah[mt], bl[n8][0], bl[n8][1]);
            }
        }
        __syncthreads();
    }

    // epilogue: bias (+lrelu), stats partials, split store to hi/lo activations
    float ps1[2][2] = {{0.f, 0.f}, {0.f, 0.f}};
    float ps2[2][2] = {{0.f, 0.f}, {0.f, 0.f}};
#pragma unroll
    for (int mt = 0; mt < 2; ++mt) {
        int o  = mb + mt * 16 + gid;
        int o2 = o + 8;
        float bi  = bp[o];
        float bi2 = bp[o2];
        size_t r1i, r2i;
        float *dh, *dl;
        if (!toAo) {
            dh = g_aeh; dl = g_ael;
            r1i = ((size_t)b * CCAT + cbase + o)  * LIN;
            r2i = ((size_t)b * CCAT + cbase + o2) * LIN;
        } else {
            dh = g_aoh; dl = g_aol;
            r1i = ((size_t)b * CO + o)  * LIN;
            r2i = ((size_t)b * CO + o2) * LIN;
        }
#pragma unroll
        for (int n8 = 0; n8 < 8; ++n8) {
            int col = l0 + nb + n8 * 8 + tg * 2;
            float v0 = acc[mt][n8][0] + bi,  v1 = acc[mt][n8][1] + bi;
            float v2 = acc[mt][n8][2] + bi2, v3 = acc[mt][n8][3] + bi2;
            if (act) {
                v0 = (v0 > 0.f) ? v0 : 0.3f * v0;
                v1 = (v1 > 0.f) ? v1 : 0.3f * v1;
                v2 = (v2 > 0.f) ? v2 : 0.3f * v2;
                v3 = (v3 > 0.f) ? v3 : 0.3f * v3;
            }
            ps1[mt][0] += v0 + v1; ps2[mt][0] += v0 * v0 + v1 * v1;
            ps1[mt][1] += v2 + v3; ps2[mt][1] += v2 * v2 + v3 * v3;
            float h0, h1, lo0, lo1;
            uint32_t t;
            t = cvt_tf32(v0); h0 = __uint_as_float(t); lo0 = __uint_as_float(cvt_tf32(v0 - h0));
            t = cvt_tf32(v1); h1 = __uint_as_float(t); lo1 = __uint_as_float(cvt_tf32(v1 - h1));
            *(float2*)&dh[r1i + col] = make_float2(h0, h1);
            *(float2*)&dl[r1i + col] = make_float2(lo0, lo1);
            t = cvt_tf32(v2); h0 = __uint_as_float(t); lo0 = __uint_as_float(cvt_tf32(v2 - h0));
            t = cvt_tf32(v3); h1 = __uint_as_float(t); lo1 = __uint_as_float(cvt_tf32(v3 - h1));
            *(float2*)&dh[r2i + col] = make_float2(h0, h1);
            *(float2*)&dl[r2i + col] = make_float2(lo0, lo1);
        }
    }
#pragma unroll
    for (int mt = 0; mt < 2; ++mt)
#pragma unroll
        for (int pr = 0; pr < 2; ++pr) {
            float a = ps1[mt][pr];
            a += __shfl_xor_sync(0xffffffffu, a, 1);
            a += __shfl_xor_sync(0xffffffffu, a, 2);
            float q = ps2[mt][pr];
            q += __shfl_xor_sync(0xffffffffu, q, 1);
            q += __shfl_xor_sync(0xffffffffu, q, 2);
            if (tg == 0) {
                int row = mb + mt * 16 + pr * 8 + gid;
                spart[wn][row][0] = a;
                spart[wn][row][1] = q;
            }
        }
    __syncthreads();
    {
        int row = tid >> 1, st = tid & 1;
        float v = spart[0][row][st] + spart[1][row][st];
        g_part[((((size_t)seg * BB + b) * 16 + blockIdx.x) * 128 + row) * 2 + st] = v;
    }
}

// ---------------- K_sf: finalize BN stats from partials ----------------
__global__ void __launch_bounds__(128) k_statsfin(
    const float* __restrict__ b2, const float* __restrict__ b3, const float* __restrict__ b4,
    const float* __restrict__ gamma, const float* __restrict__ beta)
{
    const int c = blockIdx.x, t = threadIdx.x;
    const int o = c & 127, j = c >> 7;
    const int b = t >> 4, lt = t & 15;
    size_t base = ((((size_t)j * BB + b) * 16 + lt) * 128 + o) * 2;
    float s1 = g_part[base], s2 = g_part[base + 1];
    if (j == 0) {
        size_t b4i = ((((size_t)4 * BB + b) * 16 + lt) * 128 + o) * 2;
        s1 += g_part[b4i]; s2 += g_part[b4i + 1];
    }
    __shared__ float r1[128], r2[128];
    r1[t] = s1; r2[t] = s2; __syncthreads();
    for (int s = 64; s > 0; s >>= 1) {
        if (t < s) { r1[t] += r1[t + s]; r2[t] += r2[t + s]; }
        __syncthreads();
    }
    if (t == 0) {
        float S1 = r1[0], S2 = r2[0];
        if (j > 0) {
            const float* bp = (j == 1) ? b2 : ((j == 2) ? b3 : b4);
            float z = bp[o]; z = (z > 0.f) ? z : 0.3f * z;
            S1 += 16384.f * z; S2 += 16384.f * z * z;
        }
        float mean = S1 * (1.f / 32768.f);
        float var  = S2 * (1.f / 32768.f) - mean * mean;
        float sc   = gamma[o] * rsqrtf(var + 1e-5f);
        g_scale[c] = sc;
        g_shift[c] = beta[o] - mean * sc;
    }
}

// ---------------- K3: fold BN into 1x1 weights (tf32 hi, transposed) + biases ----------------
__global__ void __launch_bounds__(256) k_fold(
    const float* __restrict__ conv_w, const float* __restrict__ conv_b,
    const float* __restrict__ b2, const float* __restrict__ b3, const float* __restrict__ b4)
{
    const int m = blockIdx.x;
    const int tid = threadIdx.x;
    float sAll = 0.f, sOdd = 0.f;
    for (int c = tid; c < CCAT; c += 256) {
        float w  = conv_w[m * CCAT + c];
        float gw = w * g_scale[c];
        g_GwTh[c * DM + m] = __uint_as_float(cvt_tf32(gw));
        sAll += w * g_shift[c];
        if (c >= 128) {
            int j = c >> 7, o = c & 127;
            const float* bp = (j == 1) ? b2 : ((j == 2) ? b3 : b4);
            float z = bp[o]; z = (z > 0.f) ? z : 0.3f * z;
            sOdd += gw * z;
        }
    }
    __shared__ float r1[256], r2[256];
    r1[tid] = sAll; r2[tid] = sOdd; __syncthreads();
    for (int s = 128; s > 0; s >>= 1) {
        if (tid < s) { r1[tid] += r1[tid + s]; r2[tid] += r2[tid + s]; }
        __syncthreads();
    }
    if (tid == 0) {
        float Gb = conv_b[m] + r1[0];
        g_Gb[m] = Gb;
        g_Gbodd[m] = Gb + r2[0];
    }
}

// ---------------- K4: merged 1x1 conv GEMM (2-stage, 2-pass split, 2 CTAs/SM) ----------------
__global__ void __launch_bounds__(256, 2) k_gemm2()
{
    extern __shared__ float dsm[];
    float* AH = dsm;                 // [2][16][SST]
    float* BH = AH + 2 * 16 * SST;
    float* BL = BH + 2 * 16 * SST;

    const int tid = threadIdx.x;
    const int b  = blockIdx.z;
    const int mode = (blockIdx.y >= 2) ? 1 : 0;
    const int m0 = (blockIdx.y & 1) * 128;
    const int l0 = blockIdx.x * 128;
    const int lane = tid & 31, wid = tid >> 5;
    const int tg = lane & 3, gid = lane >> 2;
    const int wm = wid & 3, wn = wid >> 2;
    const int mb = wm * 32, nb = wn * 64;

    const int K        = (mode == 0) ? 512 : 128;
    const size_t bstrB = (mode == 0) ? (size_t)CCAT * LIN : (size_t)CO * LIN;
    const float* BbH = ((mode == 0) ? g_aeh : g_aoh) + (size_t)b * bstrB;
    const float* BbL = ((mode == 0) ? g_ael : g_aol) + (size_t)b * bstrB;

    float acc[2][8][4];
#pragma unroll
    for (int mt = 0; mt < 2; ++mt)
#pragma unroll
        for (int n8 = 0; n8 < 8; ++n8)
#pragma unroll
            for (int q = 0; q < 4; ++q) acc[mt][n8][q] = 0.f;

    auto issue = [&](int ch) {
        const int buf = ch & 1;
        const int k0  = ch * 16;
#pragma unroll
        for (int r = 0; r < 2; ++r) {
            int e = tid + r * 256;
            int row = e >> 5, q = e & 31;
            size_t as = (size_t)(k0 + row) * DM + m0 + q * 4;
            int off = (buf * 16 + row) * SST + q * 4;
            cpa16(&AH[off], &g_GwTh[as]);
        }
#pragma unroll
        for (int r = 0; r < 2; ++r) {
            int e = tid + r * 256;
            int row = e >> 5, q = e & 31;
            size_t bs = (size_t)(k0 + row) * LIN + l0 + q * 4;
            int off = (buf * 16 + row) * SST + q * 4;
            cpa16(&BH[off], &BbH[bs]);
            cpa16(&BL[off], &BbL[bs]);
        }
    };

    issue(0); cpa_commit();
    const int NCH = K / 16;
    for (int ch = 0; ch < NCH; ++ch) {
        if (ch + 1 < NCH) issue(ch + 1);
        cpa_commit();
        cpa_wait1();
        __syncthreads();
        const int bo = (ch & 1) * 16 * SST;
#pragma unroll
        for (int kk = 0; kk < 16; kk += 8) {
            uint32_t bh[8][2], bl[8][2];
#pragma unroll
            for (int n8 = 0; n8 < 8; ++n8) {
                int c = nb + n8 * 8 + gid;
                bh[n8][0] = __float_as_uint(BH[bo + (kk + tg) * SST + c]);
                bh[n8][1] = __float_as_uint(BH[bo + (kk + tg + 4) * SST + c]);
                bl[n8][0] = __float_as_uint(BL[bo + (kk + tg) * SST + c]);
                bl[n8][1] = __float_as_uint(BL[bo + (kk + tg + 4) * SST + c]);
            }
            uint32_t ah[2][4];
#pragma unroll
            for (int mt = 0; mt < 2; ++mt) {
                int mr = mb + mt * 16;
                ah[mt][0] = __float_as_uint(AH[bo + (kk + tg) * SST + mr + gid]);
                ah[mt][1] = __float_as_uint(AH[bo + (kk + tg) * SST + mr + gid + 8]);
                ah[mt][2] = __float_as_uint(AH[bo + (kk + tg + 4) * SST + mr + gid]);
                ah[mt][3] = __float_as_uint(AH[bo + (kk + tg + 4) * SST + mr + gid + 8]);
            }
#pragma unroll
            for (int n8 = 0; n8 < 8; ++n8)
#pragma unroll
                for (int mt = 0; mt < 2; ++mt)
                    mma8(acc[mt][n8], ah[mt], bh[n8][0], bh[n8][1]);
#pragma unroll
            for (int n8 = 0; n8 < 8; ++n8)
#pragma unroll
                for (int mt = 0; mt < 2; ++mt)
                    mma8(acc[mt][n8], ah[mt], bl[n8][0], bl[n8][1]);
        }
        __syncthreads();
    }

    float* out = (mode == 0) ? g_ue : g_uo;
    const float* bias = (mode == 0) ? g_Gb : g_Gbodd;
#pragma unroll
    for (int mt = 0; mt < 2; ++mt) {
        int m  = m0 + mb + mt * 16 + gid;
        int m2 = m + 8;
        float bi  = bias[m];
        float bi2 = bias[m2];
#pragma unroll
        for (int n8 = 0; n8 < 8; ++n8) {
            int col = l0 + nb + n8 * 8 + tg * 2;
            *(float2*)&out[((size_t)(b * DM + m))  * LIN + col] =
                make_float2(acc[mt][n8][0] + bi,  acc[mt][n8][1] + bi);
            *(float2*)&out[((size_t)(b * DM + m2)) * LIN + col] =
                make_float2(acc[mt][n8][2] + bi2, acc[mt][n8][3] + bi2);
        }
    }
}

// ---------------- K5: S4D ZOH discretization -> 2nd-order real IIR coefficients ----------------
__global__ void k_s4setup(
    const float* __restrict__ A_re, const float* __restrict__ A_im,
    const float* __restrict__ log_dt,
    const float* __restrict__ C_re, const float* __restrict__ C_im)
{
    const int h = blockIdx.x, n = threadIdx.x;
    float dt  = expf(log_dt[h]);
    float ar  = A_re[h * NST + n], ai = A_im[h * NST + n];
    float dre = dt * ar, dim = dt * ai;
    float er  = expf(dre);
    float rre = er * cosf(dim), rim = er * sinf(dim);
    float d2  = ar * ar + ai * ai;
    float nre = rre - 1.f, nim = rim;
    float dbre = (nre * ar + nim * ai) / d2;
    float dbim = (nim * ar - nre * ai) / d2;
    float cr = C_re[h * NST + n], ci = C_im[h * NST + n];
    float c2re = 2.f * (cr * dbre - ci * dbim);
    float c2im = 2.f * (cr * dbim + ci * dbre);
    int idx = h * NST + n;
    g_ssm[0 * DM * NST + idx] = 2.f * rre;                    // a1
    g_ssm[1 * DM * NST + idx] = -(rre * rre + rim * rim);     // a2
    g_ssm[2 * DM * NST + idx] = c2re;                         // b0
    g_ssm[3 * DM * NST + idx] = -(c2re * rre + c2im * rim);   // b1
}

// ---------------- K6: 2-channel f32x2 IIR scan + smem-transpose reduction ----------------
// Each warp handles TWO (b,h) channels packed in f32x2 lanes (.x = A, .y = B).
__global__ void __launch_bounds__(256) k_scan(const float* __restrict__ Dv, float* __restrict__ out)
{
    extern __shared__ unsigned long long sred[];   // redE[8][32][17], redO[8][32][17]
    unsigned long long* redE = sred;
    unsigned long long* redO = sred + 8 * 32 * 17;
    const int wip  = threadIdx.x >> 5;
    const int lane = threadIdx.x & 31;
    const int wglob = blockIdx.x * 8 + wip;
    const int gA = wglob * 2, gB = gA + 1;
    const int bA = gA >> 8, hA = gA & 255;
    const int bB = gB >> 8, hB = gB & 255;
    const int iA = hA * NST + lane, iB = hB * NST + lane;

    const unsigned long long a1p = pk2(g_ssm[0 * DM * NST + iA], g_ssm[0 * DM * NST + iB]);
    const unsigned long long a2p = pk2(g_ssm[1 * DM * NST + iA], g_ssm[1 * DM * NST + iB]);
    const unsigned long long b0p = pk2(g_ssm[2 * DM * NST + iA], g_ssm[2 * DM * NST + iB]);
    const unsigned long long b1p = pk2(g_ssm[3 * DM * NST + iA], g_ssm[3 * DM * NST + iB]);
    const float DhA = Dv[hA], DhB = Dv[hB];
    const float* ueA = g_ue + ((size_t)(bA * DM + hA)) * LIN;
    const float* uoA = g_uo + ((size_t)(bA * DM + hA)) * LIN;
    const float* ueB = g_ue + ((size_t)(bB * DM + hB)) * LIN;
    const float* uoB = g_uo + ((size_t)(bB * DM + hB)) * LIN;
    float* opA = out + ((size_t)(bA * DM + hA)) * LOUT;
    float* opB = out + ((size_t)(bB * DM + hB)) * LOUT;

    unsigned long long* myE = redE + (wip * 32 + lane) * 17;
    unsigned long long* myO = redO + (wip * 32 + lane) * 17;

    unsigned long long gp1 = 0ull, gp2 = 0ull, up = 0ull;
    for (int l0 = 0; l0 < LIN; l0 += 16) {
        float uaA[16], ubA[16], uaB[16], ubB[16];
#pragma unroll
        for (int q = 0; q < 4; ++q) {
            float4 t0 = __ldg((const float4*)(ueA + l0) + q);
            float4 t1 = __ldg((const float4*)(uoA + l0) + q);
            float4 t2 = __ldg((const float4*)(ueB + l0) + q);
            float4 t3 = __ldg((const float4*)(uoB + l0) + q);
            uaA[4 * q + 0] = t0.x; uaA[4 * q + 1] = t0.y; uaA[4 * q + 2] = t0.z; uaA[4 * q + 3] = t0.w;
            ubA[4 * q + 0] = t1.x; ubA[4 * q + 1] = t1.y; ubA[4 * q + 2] = t1.z; ubA[4 * q + 3] = t1.w;
            uaB[4 * q + 0] = t2.x; uaB[4 * q + 1] = t2.y; uaB[4 * q + 2] = t2.z; uaB[4 * q + 3] = t2.w;
            ubB[4 * q + 0] = t3.x; ubB[4 * q + 1] = t3.y; ubB[4 * q + 2] = t3.z; ubB[4 * q + 3] = t3.w;
        }
#pragma unroll
        for (int i = 0; i < 16; ++i) {
            unsigned long long u0 = pk2(uaA[i], uaB[i]);
            unsigned long long u1 = pk2(ubA[i], ubB[i]);
            unsigned long long ge = fma2d(a1p, gp1, fma2d(a2p, gp2, fma2d(b0p, u0, mul2d(b1p, up))));
            unsigned long long go = fma2d(a1p, ge,  fma2d(a2p, gp1, fma2d(b0p, u1, mul2d(b1p, u0))));
            gp2 = ge; gp1 = go; up = u1;
            myE[i] = ge;
            myO[i] = go;
        }
        __syncwarp();
        const int r0 = (lane < 16) ? 0 : 16;
        const int col = lane & 15;
        const unsigned long long* pe = redE + (wip * 32 + r0) * 17 + col;
        const unsigned long long* po = redO + (wip * 32 + r0) * 17 + col;
        unsigned long long sE = 0ull, sO = 0ull;
#pragma unroll
        for (int j = 0; j < 16; ++j) {
            asm("add.rn.f32x2 %0, %0, %1;" : "+l"(sE) : "l"(pe[0]));
            asm("add.rn.f32x2 %0, %0, %1;" : "+l"(sO) : "l"(po[0]));
            pe += 17; po += 17;
        }
        float2 fE = upk2(sE), fO = upk2(sO);
        fE.x += __shfl_xor_sync(0xffffffffu, fE.x, 16);
        fE.y += __shfl_xor_sync(0xffffffffu, fE.y, 16);
        fO.x += __shfl_xor_sync(0xffffffffu, fO.x, 16);
        fO.y += __shfl_xor_sync(0xffffffffu, fO.y, 16);
        if (lane < 16) {
            int li = l0 + col;
            float2 yA, yB;
            yA.x = fmaf(DhA, __ldg(&ueA[li]), fE.x);
            yA.y = fmaf(DhA, __ldg(&uoA[li]), fO.x);
            yB.x = fmaf(DhB, __ldg(&ueB[li]), fE.y);
            yB.y = fmaf(DhB, __ldg(&uoB[li]), fO.y);
            *(float2*)&opA[2 * li] = yA;
            *(float2*)&opB[2 * li] = yB;
        }
        __syncwarp();
    }
}

extern "C" void kernel_launch(void* const* d_in, const int* in_sizes, int n_in,
                              void* d_out, int out_size) {
    (void)in_sizes; (void)n_in; (void)out_size;
    const float* x        = (const float*)d_in[0];
    const float* w1       = (const float*)d_in[1];
    const float* b1       = (const float*)d_in[2];
    const float* w2       = (const float*)d_in[3];
    const float* b2       = (const float*)d_in[4];
    const float* w3       = (const float*)d_in[5];
    const float* b3       = (const float*)d_in[6];
    const float* w4       = (const float*)d_in[7];
    const float* b4       = (const float*)d_in[8];
    const float* bn_gamma = (const float*)d_in[9];
    const float* bn_beta  = (const float*)d_in[10];
    const float* conv_w   = (const float*)d_in[11];
    const float* conv_b   = (const float*)d_in[12];
    const float* A_re     = (const float*)d_in[13];
    const float* A_im     = (const float*)d_in[14];
    const float* log_dt   = (const float*)d_in[15];
    const float* C_re     = (const float*)d_in[16];
    const float* C_im     = (const float*)d_in[17];
    const float* Dv       = (const float*)d_in[18];
    float* out = (float*)d_out;

    const int k1_smem = 4 * 2 * 16 * SST * 4;       // 69632 B
    const int g2_smem = 3 * 2 * 16 * SST * 4;       // 52224 B
    const int sc_smem = 2 * 8 * 32 * 17 * 8;        // 69632 B
    cudaFuncSetAttribute(k1_deconv, cudaFuncAttributeMaxDynamicSharedMemorySize, k1_smem);
    cudaFuncSetAttribute(k_gemm2,   cudaFuncAttributeMaxDynamicSharedMemorySize, g2_smem);
    cudaFuncSetAttribute(k_scan,    cudaFuncAttributeMaxDynamicSharedMemorySize, sc_smem);

    k_s4setup<<<DM, NST>>>(A_re, A_im, log_dt, C_re, C_im);
    k_wprep<<<512, 256>>>(w1, w2, w3, w4);
    k_xprep<<<2048, 256>>>(x);
    k1_deconv<<<dim3(LIN / 128, 5, BB), 256, k1_smem>>>(b1, b2, b3, b4);
    k_statsfin<<<CCAT, 128>>>(b2, b3, b4, bn_gamma, bn_beta);
    k_fold<<<DM, 256>>>(conv_w, conv_b, b2, b3, b4);
    k_gemm2<<<dim3(LIN / 128, 4, BB), 256, g2_smem>>>();
    k_scan<<<(BB * DM) / 16, 256, sc_smem>>>(Dv, out);
}

// round 17
// speedup vs baseline: 1.2040x; 1.2040x over previous
#include <cuda_runtime.h>
#include <cstdint>
#include <cstddef>

#define BB    8
#define CIN   128
#define CO    128
#define LIN   2048
#define LOUT  4096
#define CCAT  512
#define DM    256
#define NST   32
#define SST   136   // smem row stride (floats): conflict-free

// ---------------- device scratch (static: allocation-free) ----------------
__device__ float g_xh[(size_t)BB * CIN * LIN];    // tf32-split input x
__device__ float g_xl[(size_t)BB * CIN * LIN];
__device__ float g_wkh[8 * 128 * 128];            // packed deconv weights (tf32 hi)
__device__ float g_aeh[(size_t)BB * CCAT * LIN];  // split even-position activations
__device__ float g_ael[(size_t)BB * CCAT * LIN];
__device__ float g_aoh[(size_t)BB * CO * LIN];    // split odd-position (branch-1 tap1)
__device__ float g_aol[(size_t)BB * CO * LIN];
__device__ float g_part[5 * BB * 16 * 128 * 2];   // per-block stats partials
__device__ float g_scale[CCAT];
__device__ float g_shift[CCAT];
__device__ float g_GwTh[CCAT * DM];               // folded 1x1 weights [c][m] (tf32 hi)
__device__ float g_Gb[DM];
__device__ float g_Gbodd[DM];
__device__ float g_ue[(size_t)BB * DM * LIN];
__device__ float g_uo[(size_t)BB * DM * LIN];
__device__ float g_ssm[4 * DM * NST];             // a1, a2, b0, b1 (2nd-order real IIR)

// ---------------- tf32 helpers ----------------
__device__ __forceinline__ uint32_t cvt_tf32(float x) {
    uint32_t r;
    asm("cvt.rna.tf32.f32 %0, %1;" : "=r"(r) : "f"(x));
    return r;
}
__device__ __forceinline__ void mma8(float* d, const uint32_t* a, uint32_t b0, uint32_t b1) {
    asm("mma.sync.aligned.m16n8k8.row.col.f32.tf32.tf32.f32 "
        "{%0,%1,%2,%3}, {%4,%5,%6,%7}, {%8,%9}, {%0,%1,%2,%3};"
        : "+f"(d[0]), "+f"(d[1]), "+f"(d[2]), "+f"(d[3])
        : "r"(a[0]), "r"(a[1]), "r"(a[2]), "r"(a[3]), "r"(b0), "r"(b1));
}
__device__ __forceinline__ float2 upk2(unsigned long long v) {
    float2 f;
    asm("mov.b64 {%0, %1}, %2;" : "=f"(f.x), "=f"(f.y) : "l"(v));
    return f;
}

// ---------------- cp.async helpers ----------------
__device__ __forceinline__ void cpa16(void* dst, const void* src) {
    unsigned ds = (unsigned)__cvta_generic_to_shared(dst);
    asm volatile("cp.async.cg.shared.global [%0], [%1], 16;" :: "r"(ds), "l"(src));
}
__device__ __forceinline__ void cpa_commit() { asm volatile("cp.async.commit_group;"); }
__device__ __forceinline__ void cpa_wait1()  { asm volatile("cp.async.wait_group 1;"); }

// ---------------- K_prep: fused x-split + weight-pack + SSM setup ----------------
// blocks [0, 2048):    x split (tf32 hi/lo)
// blocks [2048, 2560): deconv weight pack (tf32 hi)
// blocks [2560, 2592): S4D ZOH -> 2nd-order IIR coefficients
__global__ void k_prep(
    const float* __restrict__ x,
    const float* __restrict__ w1, const float* __restrict__ w2,
    const float* __restrict__ w3, const float* __restrict__ w4,
    const float* __restrict__ A_re, const float* __restrict__ A_im,
    const float* __restrict__ log_dt,
    const float* __restrict__ C_re, const float* __restrict__ C_im)
{
    const int blk = blockIdx.x;
    if (blk < 2048) {
        size_t i = ((size_t)blk * 256 + threadIdx.x) * 4;
        float4 v = *(const float4*)&x[i];
        float4 h, l;
        uint32_t t;
        t = cvt_tf32(v.x); h.x = __uint_as_float(t); l.x = __uint_as_float(cvt_tf32(v.x - h.x));
        t = cvt_tf32(v.y); h.y = __uint_as_float(t); l.y = __uint_as_float(cvt_tf32(v.y - h.y));
        t = cvt_tf32(v.z); h.z = __uint_as_float(t); l.z = __uint_as_float(cvt_tf32(v.z - h.z));
        t = cvt_tf32(v.w); h.w = __uint_as_float(t); l.w = __uint_as_float(cvt_tf32(v.w - h.w));
        *(float4*)&g_xh[i] = h;
        *(float4*)&g_xl[i] = l;
    } else if (blk < 2560) {
        int idx = (blk - 2048) * 256 + threadIdx.x;
        int plane = idx >> 14;
        int r = idx & 16383;
        const float* w; int tap;
        switch (plane) {
            case 0: w = w1; tap = 0; break;
            case 1: w = w2; tap = 0; break;
            case 2: w = w2; tap = 1; break;
            case 3: w = w3; tap = 0; break;
            case 4: w = w3; tap = 1; break;
            case 5: w = w4; tap = 0; break;
            case 6: w = w4; tap = 1; break;
            default: w = w1; tap = 1; break;
        }
        g_wkh[idx] = __uint_as_float(cvt_tf32(w[r * 2 + tap]));
    } else {
        int t = (blk - 2560) * 256 + threadIdx.x;   // 0 .. 8191
        int h = t >> 5, n = t & 31;
        float dt  = expf(log_dt[h]);
        float ar  = A_re[h * NST + n], ai = A_im[h * NST + n];
        float dre = dt * ar, dim = dt * ai;
        float er  = expf(dre);
        float rre = er * cosf(dim), rim = er * sinf(dim);
        float d2  = ar * ar + ai * ai;
        float nre = rre - 1.f, nim = rim;
        float dbre = (nre * ar + nim * ai) / d2;
        float dbim = (nim * ar - nre * ai) / d2;
        float cr = C_re[h * NST + n], ci = C_im[h * NST + n];
        float c2re = 2.f * (cr * dbre - ci * dbim);
        float c2im = 2.f * (cr * dbim + ci * dbre);
        int idx = h * NST + n;
        g_ssm[0 * DM * NST + idx] = 2.f * rre;                    // a1
        g_ssm[1 * DM * NST + idx] = -(rre * rre + rim * rim);     // a2
        g_ssm[2 * DM * NST + idx] = c2re;                         // b0
        g_ssm[3 * DM * NST + idx] = -(c2re * rre + c2im * rim);   // b1
    }
}

// ---------------- K1: fused deconv GEMMs (2-stage, K-chunk = 16 channels) ----------------
__global__ void __launch_bounds__(256) k1_deconv(
    const float* __restrict__ b1, const float* __restrict__ b2,
    const float* __restrict__ b3, const float* __restrict__ b4)
{
    extern __shared__ float dsm[];
    float* XH  = dsm;               // [2][16][SST]
    float* XL  = XH  + 2 * 16 * SST;
    float* W0H = XL  + 2 * 16 * SST;
    float* W1H = W0H + 2 * 16 * SST;
    __shared__ float spart[2][128][2];

    const int tid = threadIdx.x;
    const int b   = blockIdx.z;
    const int seg = blockIdx.y;
    const int l0  = blockIdx.x * 128;
    const int lane = tid & 31, wid = tid >> 5;
    const int tg = lane & 3, gid = lane >> 2;
    const int wm = wid & 3, wn = wid >> 2;
    const int mb = wm * 32, nb = wn * 64;

    int p0, p1, dj, cbase; bool act, toAo;
    const float* bp;
    switch (seg) {
        case 0:  p0 = 0; p1 = -1; dj = 0; act = false; toAo = false; cbase = 0;   bp = b1; break;
        case 1:  p0 = 1; p1 = 2;  dj = 1; act = true;  toAo = false; cbase = 128; bp = b2; break;
        case 2:  p0 = 3; p1 = 4;  dj = 2; act = true;  toAo = false; cbase = 256; bp = b3; break;
        case 3:  p0 = 5; p1 = 6;  dj = 4; act = true;  toAo = false; cbase = 384; bp = b4; break;
        default: p0 = 7; p1 = -1; dj = 0; act = false; toAo = true;  cbase = 0;   bp = b1; break;
    }
    const bool dual = (p1 >= 0);

    float acc[2][8][4];
#pragma unroll
    for (int mt = 0; mt < 2; ++mt)
#pragma unroll
        for (int n8 = 0; n8 < 8; ++n8)
#pragma unroll
            for (int q = 0; q < 4; ++q) acc[mt][n8][q] = 0.f;

    auto issue = [&](int ch) {
        const int buf = ch & 1;
        const int c0  = ch * 16;
        for (int e = tid; e < 528; e += 256) {
            int row = e / 33;
            int q   = e - row * 33;
            int off = (buf * 16 + row) * SST + q * 4;
            if (l0 == 0 && q == 0) {
                *(float4*)&XH[off] = make_float4(0.f, 0.f, 0.f, 0.f);
                *(float4*)&XL[off] = make_float4(0.f, 0.f, 0.f, 0.f);
            } else {
                size_t src = (size_t)(b * 128 + c0 + row) * LIN + l0 - 4 + q * 4;
                cpa16(&XH[off], &g_xh[src]);
                cpa16(&XL[off], &g_xl[src]);
            }
        }
#pragma unroll
        for (int r = 0; r < 2; ++r) {
            int e = tid + r * 256;
            int row = e >> 5, q = e & 31;
            int woff = (buf * 16 + row) * SST + q * 4;
            size_t ws0 = (size_t)p0 * 16384 + (c0 + row) * 128 + q * 4;
            cpa16(&W0H[woff], &g_wkh[ws0]);
            if (dual) {
                size_t ws1 = (size_t)p1 * 16384 + (c0 + row) * 128 + q * 4;
                cpa16(&W1H[woff], &g_wkh[ws1]);
            }
        }
    };

    issue(0); cpa_commit();
    const int NCH = 8;
    for (int ch = 0; ch < NCH; ++ch) {
        if (ch + 1 < NCH) issue(ch + 1);
        cpa_commit();
        cpa_wait1();
        __syncthreads();
        const int bo = (ch & 1) * 16 * SST;

#pragma unroll
        for (int kk = 0; kk < 16; kk += 8) {
            uint32_t bh[8][2], bl[8][2];
#pragma unroll
            for (int n8 = 0; n8 < 8; ++n8) {
                int c = 4 + nb + n8 * 8 + gid;
                bh[n8][0] = __float_as_uint(XH[bo + (kk + tg) * SST + c]);
                bh[n8][1] = __float_as_uint(XH[bo + (kk + tg + 4) * SST + c]);
                bl[n8][0] = __float_as_uint(XL[bo + (kk + tg) * SST + c]);
                bl[n8][1] = __float_as_uint(XL[bo + (kk + tg + 4) * SST + c]);
            }
            uint32_t ah[2][4];
#pragma unroll
            for (int mt = 0; mt < 2; ++mt) {
                int mr = mb + mt * 16;
                ah[mt][0] = __float_as_uint(W0H[bo + (kk + tg) * SST + mr + gid]);
                ah[mt][1] = __float_as_uint(W0H[bo + (kk + tg) * SST + mr + gid + 8]);
                ah[mt][2] = __float_as_uint(W0H[bo + (kk + tg + 4) * SST + mr + gid]);
                ah[mt][3] = __float_as_uint(W0H[bo + (kk + tg + 4) * SST + mr + gid + 8]);
            }
#pragma unroll
            for (int n8 = 0; n8 < 8; ++n8)
#pragma unroll
                for (int mt = 0; mt < 2; ++mt)
                    mma8(acc[mt][n8], ah[mt], bh[n8][0], bh[n8][1]);
#pragma unroll
            for (int n8 = 0; n8 < 8; ++n8)
#pragma unroll
                for (int mt = 0; mt < 2; ++mt)
                    mma8(acc[mt][n8], ah[mt], bl[n8][0], bl[n8][1]);

            if (dual) {
                const int off = 4 - dj;
#pragma unroll
                for (int n8 = 0; n8 < 8; ++n8) {
                    int c = off + nb + n8 * 8 + gid;
                    bh[n8][0] = __float_as_uint(XH[bo + (kk + tg) * SST + c]);
                    bh[n8][1] = __float_as_uint(XH[bo + (kk + tg + 4) * SST + c]);
                    bl[n8][0] = __float_as_uint(XL[bo + (kk + tg) * SST + c]);
                    bl[n8][1] = __float_as_uint(XL[bo + (kk + tg + 4) * SST + c]);
                }
#pragma unroll
                for (int mt = 0; mt < 2; ++mt) {
                    int mr = mb + mt * 16;
                    ah[mt][0] = __float_as_uint(W1H[bo + (kk + tg) * SST + mr + gid]);
                    ah[mt][1] = __float_as_uint(W1H[bo + (kk + tg) * SST + mr + gid + 8]);
                    ah[mt][2] = __float_as_uint(W1H[bo + (kk + tg + 4) * SST + mr + gid]);
                    ah[mt][3] = __float_as_uint(W1H[bo + (kk + tg + 4) * SST + mr + gid + 8]);
                }
#pragma unroll
                for (int n8 = 0; n8 < 8; ++n8)
#pragma unroll
                    for (int mt = 0; mt < 2; ++mt)
                        mma8(acc[mt][n8], ah[mt], bh[n8][0], bh[n8][1]);
#pragma unroll
                for (int n8 = 0; n8 < 8; ++n8)
#pragma unroll
                    for (int mt = 0; mt < 2; ++mt)
                        mma8(acc[mt][n8], ah[mt], bl[n8][0], bl[n8][1]);
            }
        }
        __syncthreads();
    }

    // epilogue: bias (+lrelu), stats partials, split store to hi/lo activations
    float ps1[2][2] = {{0.f, 0.f}, {0.f, 0.f}};
    float ps2[2][2] = {{0.f, 0.f}, {0.f, 0.f}};
#pragma unroll
    for (int mt = 0; mt < 2; ++mt) {
        int o  = mb + mt * 16 + gid;
        int o2 = o + 8;
        float bi  = bp[o];
        float bi2 = bp[o2];
        size_t r1i, r2i;
        float *dh, *dl;
        if (!toAo) {
            dh = g_aeh; dl = g_ael;
            r1i = ((size_t)b * CCAT + cbase + o)  * LIN;
            r2i = ((size_t)b * CCAT + cbase + o2) * LIN;
        } else {
            dh = g_aoh; dl = g_aol;
            r1i = ((size_t)b * CO + o)  * LIN;
            r2i = ((size_t)b * CO + o2) * LIN;
        }
#pragma unroll
        for (int n8 = 0; n8 < 8; ++n8) {
            int col = l0 + nb + n8 * 8 + tg * 2;
            float v0 = acc[mt][n8][0] + bi,  v1 = acc[mt][n8][1] + bi;
            float v2 = acc[mt][n8][2] + bi2, v3 = acc[mt][n8][3] + bi2;
            if (act) {
                v0 = (v0 > 0.f) ? v0 : 0.3f * v0;
                v1 = (v1 > 0.f) ? v1 : 0.3f * v1;
                v2 = (v2 > 0.f) ? v2 : 0.3f * v2;
                v3 = (v3 > 0.f) ? v3 : 0.3f * v3;
            }
            ps1[mt][0] += v0 + v1; ps2[mt][0] += v0 * v0 + v1 * v1;
            ps1[mt][1] += v2 + v3; ps2[mt][1] += v2 * v2 + v3 * v3;
            float h0, h1, lo0, lo1;
            uint32_t t;
            t = cvt_tf32(v0); h0 = __uint_as_float(t); lo0 = __uint_as_float(cvt_tf32(v0 - h0));
            t = cvt_tf32(v1); h1 = __uint_as_float(t); lo1 = __uint_as_float(cvt_tf32(v1 - h1));
            *(float2*)&dh[r1i + col] = make_float2(h0, h1);
            *(float2*)&dl[r1i + col] = make_float2(lo0, lo1);
            t = cvt_tf32(v2); h0 = __uint_as_float(t); lo0 = __uint_as_float(cvt_tf32(v2 - h0));
            t = cvt_tf32(v3); h1 = __uint_as_float(t); lo1 = __uint_as_float(cvt_tf32(v3 - h1));
            *(float2*)&dh[r2i + col] = make_float2(h0, h1);
            *(float2*)&dl[r2i + col] = make_float2(lo0, lo1);
        }
    }
#pragma unroll
    for (int mt = 0; mt < 2; ++mt)
#pragma unroll
        for (int pr = 0; pr < 2; ++pr) {
            float a = ps1[mt][pr];
            a += __shfl_xor_sync(0xffffffffu, a, 1);
            a += __shfl_xor_sync(0xffffffffu, a, 2);
            float q = ps2[mt][pr];
            q += __shfl_xor_sync(0xffffffffu, q, 1);
            q += __shfl_xor_sync(0xffffffffu, q, 2);
            if (tg == 0) {
                int row = mb + mt * 16 + pr * 8 + gid;
                spart[wn][row][0] = a;
                spart[wn][row][1] = q;
            }
        }
    __syncthreads();
    {
        int row = tid >> 1, st = tid & 1;
        float v = spart[0][row][st] + spart[1][row][st];
        g_part[((((size_t)seg * BB + b) * 16 + blockIdx.x) * 128 + row) * 2 + st] = v;
    }
}

// ---------------- K_sf: finalize BN stats from partials ----------------
__global__ void __launch_bounds__(128) k_statsfin(
    const float* __restrict__ b2, const float* __restrict__ b3, const float* __restrict__ b4,
    const float* __restrict__ gamma, const float* __restrict__ beta)
{
    const int c = blockIdx.x, t = threadIdx.x;
    const int o = c & 127, j = c >> 7;
    const int b = t >> 4, lt = t & 15;
    size_t base = ((((size_t)j * BB + b) * 16 + lt) * 128 + o) * 2;
    float s1 = g_part[base], s2 = g_part[base + 1];
    if (j == 0) {
        size_t b4i = ((((size_t)4 * BB + b) * 16 + lt) * 128 + o) * 2;
        s1 += g_part[b4i]; s2 += g_part[b4i + 1];
    }
    __shared__ float r1[128], r2[128];
    r1[t] = s1; r2[t] = s2; __syncthreads();
    for (int s = 64; s > 0; s >>= 1) {
        if (t < s) { r1[t] += r1[t + s]; r2[t] += r2[t + s]; }
        __syncthreads();
    }
    if (t == 0) {
        float S1 = r1[0], S2 = r2[0];
        if (j > 0) {
            const float* bp = (j == 1) ? b2 : ((j == 2) ? b3 : b4);
            float z = bp[o]; z = (z > 0.f) ? z : 0.3f * z;
            S1 += 16384.f * z; S2 += 16384.f * z * z;
        }
        float mean = S1 * (1.f / 32768.f);
        float var  = S2 * (1.f / 32768.f) - mean * mean;
        float sc   = gamma[o] * rsqrtf(var + 1e-5f);
        g_scale[c] = sc;
        g_shift[c] = beta[o] - mean * sc;
    }
}

// ---------------- K3: fold BN into 1x1 weights (tf32 hi, transposed) + biases ----------------
__global__ void __launch_bounds__(256) k_fold(
    const float* __restrict__ conv_w, const float* __restrict__ conv_b,
    const float* __restrict__ b2, const float* __restrict__ b3, const float* __restrict__ b4)
{
    const int m = blockIdx.x;
    const int tid = threadIdx.x;
    float sAll = 0.f, sOdd = 0.f;
    for (int c = tid; c < CCAT; c += 256) {
        float w  = conv_w[m * CCAT + c];
        float gw = w * g_scale[c];
        g_GwTh[c * DM + m] = __uint_as_float(cvt_tf32(gw));
        sAll += w * g_shift[c];
        if (c >= 128) {
            int j = c >> 7, o = c & 127;
            const float* bp = (j == 1) ? b2 : ((j == 2) ? b3 : b4);
            float z = bp[o]; z = (z > 0.f) ? z : 0.3f * z;
            sOdd += gw * z;
        }
    }
    __shared__ float r1[256], r2[256];
    r1[tid] = sAll; r2[tid] = sOdd; __syncthreads();
    for (int s = 128; s > 0; s >>= 1) {
        if (tid < s) { r1[tid] += r1[tid + s]; r2[tid] += r2[tid + s]; }
        __syncthreads();
    }
    if (tid == 0) {
        float Gb = conv_b[m] + r1[0];
        g_Gb[m] = Gb;
        g_Gbodd[m] = Gb + r2[0];
    }
}

// ---------------- K4: merged 1x1 conv GEMM (2-stage, 2-pass split, 2 CTAs/SM) ----------------
__global__ void __launch_bounds__(256, 2) k_gemm2()
{
    extern __shared__ float dsm[];
    float* AH = dsm;                 // [2][16][SST]
    float* BH = AH + 2 * 16 * SST;
    float* BL = BH + 2 * 16 * SST;

    const int tid = threadIdx.x;
    const int b  = blockIdx.z;
    const int mode = (blockIdx.y >= 2) ? 1 : 0;
    const int m0 = (blockIdx.y & 1) * 128;
    const int l0 = blockIdx.x * 128;
    const int lane = tid & 31, wid = tid >> 5;
    const int tg = lane & 3, gid = lane >> 2;
    const int wm = wid & 3, wn = wid >> 2;
    const int mb = wm * 32, nb = wn * 64;

    const int K        = (mode == 0) ? 512 : 128;
    const size_t bstrB = (mode == 0) ? (size_t)CCAT * LIN : (size_t)CO * LIN;
    const float* BbH = ((mode == 0) ? g_aeh : g_aoh) + (size_t)b * bstrB;
    const float* BbL = ((mode == 0) ? g_ael : g_aol) + (size_t)b * bstrB;

    float acc[2][8][4];
#pragma unroll
    for (int mt = 0; mt < 2; ++mt)
#pragma unroll
        for (int n8 = 0; n8 < 8; ++n8)
#pragma unroll
            for (int q = 0; q < 4; ++q) acc[mt][n8][q] = 0.f;

    auto issue = [&](int ch) {
        const int buf = ch & 1;
        const int k0  = ch * 16;
#pragma unroll
        for (int r = 0; r < 2; ++r) {
            int e = tid + r * 256;
            int row = e >> 5, q = e & 31;
            size_t as = (size_t)(k0 + row) * DM + m0 + q * 4;
            int off = (buf * 16 + row) * SST + q * 4;
            cpa16(&AH[off], &g_GwTh[as]);
        }
#pragma unroll
        for (int r = 0; r < 2; ++r) {
            int e = tid + r * 256;
            int row = e >> 5, q = e & 31;
            size_t bs = (size_t)(k0 + row) * LIN + l0 + q * 4;
            int off = (buf * 16 + row) * SST + q * 4;
            cpa16(&BH[off], &BbH[bs]);
            cpa16(&BL[off], &BbL[bs]);
        }
    };

    issue(0); cpa_commit();
    const int NCH = K / 16;
    for (int ch = 0; ch < NCH; ++ch) {
        if (ch + 1 < NCH) issue(ch + 1);
        cpa_commit();
        cpa_wait1();
        __syncthreads();
        const int bo = (ch & 1) * 16 * SST;
#pragma unroll
        for (int kk = 0; kk < 16; kk += 8) {
            uint32_t bh[8][2], bl[8][2];
#pragma unroll
            for (int n8 = 0; n8 < 8; ++n8) {
                int c = nb + n8 * 8 + gid;
                bh[n8][0] = __float_as_uint(BH[bo + (kk + tg) * SST + c]);
                bh[n8][1] = __float_as_uint(BH[bo + (kk + tg + 4) * SST + c]);
                bl[n8][0] = __float_as_uint(BL[bo + (kk + tg) * SST + c]);
                bl[n8][1] = __float_as_uint(BL[bo + (kk + tg + 4) * SST + c]);
            }
            uint32_t ah[2][4];
#pragma unroll
            for (int mt = 0; mt < 2; ++mt) {
                int mr = mb + mt * 16;
                ah[mt][0] = __float_as_uint(AH[bo + (kk + tg) * SST + mr + gid]);
                ah[mt][1] = __float_as_uint(AH[bo + (kk + tg) * SST + mr + gid + 8]);
                ah[mt][2] = __float_as_uint(AH[bo + (kk + tg + 4) * SST + mr + gid]);
                ah[mt][3] = __float_as_uint(AH[bo + (kk + tg + 4) * SST + mr + gid + 8]);
            }
#pragma unroll
            for (int n8 = 0; n8 < 8; ++n8)
#pragma unroll
                for (int mt = 0; mt < 2; ++mt)
                    mma8(acc[mt][n8], ah[mt], bh[n8][0], bh[n8][1]);
#pragma unroll
            for (int n8 = 0; n8 < 8; ++n8)
#pragma unroll
                for (int mt = 0; mt < 2; ++mt)
                    mma8(acc[mt][n8], ah[mt], bl[n8][0], bl[n8][1]);
        }
        __syncthreads();
    }

    float* out = (mode == 0) ? g_ue : g_uo;
    const float* bias = (mode == 0) ? g_Gb : g_Gbodd;
#pragma unroll
    for (int mt = 0; mt < 2; ++mt) {
        int m  = m0 + mb + mt * 16 + gid;
        int m2 = m + 8;
        float bi  = bias[m];
        float bi2 = bias[m2];
#pragma unroll
        for (int n8 = 0; n8 < 8; ++n8) {
            int col = l0 + nb + n8 * 8 + tg * 2;
            *(float2*)&out[((size_t)(b * DM + m))  * LIN + col] =
                make_float2(acc[mt][n8][0] + bi,  acc[mt][n8][1] + bi);
            *(float2*)&out[((size_t)(b * DM + m2)) * LIN + col] =
                make_float2(acc[mt][n8][2] + bi2, acc[mt][n8][3] + bi2);
        }
    }
}

// ---------------- K6: SSM scan via 2nd-order IIR + smem-transpose reduction ----------------
__global__ void __launch_bounds__(256) k_scan(const float* __restrict__ Dv, float* __restrict__ out)
{
    __shared__ float2 red[8][32][17];
    const int wip  = threadIdx.x >> 5;
    const int w    = blockIdx.x * 8 + wip;
    const int lane = threadIdx.x & 31;
    const int b = w >> 8, h = w & 255;
    const int idx = h * NST + lane;
    const float a1 = g_ssm[0 * DM * NST + idx];
    const float a2 = g_ssm[1 * DM * NST + idx];
    const float b0 = g_ssm[2 * DM * NST + idx];
    const float b1 = g_ssm[3 * DM * NST + idx];
    const float Dh = Dv[h];
    const float* ue = g_ue + ((size_t)(b * DM + h)) * LIN;
    const float* uo = g_uo + ((size_t)(b * DM + h)) * LIN;
    float* op = out + ((size_t)(b * DM + h)) * LOUT;

    float gp1 = 0.f, gp2 = 0.f, up = 0.f;   // g_{t-1}, g_{t-2}, u_{t-1}
    for (int l0 = 0; l0 < LIN; l0 += 16) {
        float ua[16], ub[16];
#pragma unroll
        for (int q = 0; q < 4; ++q) {
            float4 t0 = __ldg((const float4*)(ue + l0) + q);
            float4 t1 = __ldg((const float4*)(uo + l0) + q);
            ua[4 * q + 0] = t0.x; ua[4 * q + 1] = t0.y; ua[4 * q + 2] = t0.z; ua[4 * q + 3] = t0.w;
            ub[4 * q + 0] = t1.x; ub[4 * q + 1] = t1.y; ub[4 * q + 2] = t1.z; ub[4 * q + 3] = t1.w;
        }
#pragma unroll
        for (int i = 0; i < 16; ++i) {
            float u0 = ua[i], u1 = ub[i];
            float ge = fmaf(a1, gp1, fmaf(a2, gp2, fmaf(b0, u0, b1 * up)));
            float go = fmaf(a1, ge,  fmaf(a2, gp1, fmaf(b0, u1, b1 * u0)));
            gp2 = ge; gp1 = go; up = u1;
            red[wip][lane][i] = make_float2(ge, go);
        }
        __syncwarp();
        const float2* rp = &red[wip][(lane < 16) ? 0 : 16][lane & 15];
        unsigned long long sacc = 0ull;
#pragma unroll
        for (int j = 0; j < 16; ++j) {
            unsigned long long v = *(const unsigned long long*)rp;
            asm("add.rn.f32x2 %0, %0, %1;" : "+l"(sacc) : "l"(v));
            rp += 17;
        }
        float2 f = upk2(sacc);
        f.x += __shfl_xor_sync(0xffffffffu, f.x, 16);
        f.y += __shfl_xor_sync(0xffffffffu, f.y, 16);
        if (lane < 16) {
            int li = l0 + lane;
            float2 yv;
            yv.x = fmaf(Dh, __ldg(&ue[li]), f.x);
            yv.y = fmaf(Dh, __ldg(&uo[li]), f.y);
            *(float2*)&op[2 * li] = yv;
        }
        __syncwarp();
    }
}

extern "C" void kernel_launch(void* const* d_in, const int* in_sizes, int n_in,
                              void* d_out, int out_size) {
    (void)in_sizes; (void)n_in; (void)out_size;
    const float* x        = (const float*)d_in[0];
    const float* w1       = (const float*)d_in[1];
    const float* b1       = (const float*)d_in[2];
    const float* w2       = (const float*)d_in[3];
    const float* b2       = (const float*)d_in[4];
    const float* w3       = (const float*)d_in[5];
    const float* b3       = (const float*)d_in[6];
    const float* w4       = (const float*)d_in[7];
    const float* b4       = (const float*)d_in[8];
    const float* bn_gamma = (const float*)d_in[9];
    const float* bn_beta  = (const float*)d_in[10];
    const float* conv_w   = (const float*)d_in[11];
    const float* conv_b   = (const float*)d_in[12];
    const float* A_re     = (const float*)d_in[13];
    const float* A_im     = (const float*)d_in[14];
    const float* log_dt   = (const float*)d_in[15];
    const float* C_re     = (const float*)d_in[16];
    const float* C_im     = (const float*)d_in[17];
    const float* Dv       = (const float*)d_in[18];
    float* out = (float*)d_out;

    const int k1_smem = 4 * 2 * 16 * SST * 4;     // 69632 B
    const int g2_smem = 3 * 2 * 16 * SST * 4;     // 52224 B
    cudaFuncSetAttribute(k1_deconv, cudaFuncAttributeMaxDynamicSharedMemorySize, k1_smem);
    cudaFuncSetAttribute(k_gemm2,   cudaFuncAttributeMaxDynamicSharedMemorySize, g2_smem);

    k_prep<<<2592, 256>>>(x, w1, w2, w3, w4, A_re, A_im, log_dt, C_re, C_im);
    k1_deconv<<<dim3(LIN / 128, 5, BB), 256, k1_smem>>>(b1, b2, b3, b4);
    k_statsfin<<<CCAT, 128>>>(b2, b3, b4, bn_gamma, bn_beta);
    k_fold<<<DM, 256>>>(conv_w, conv_b, b2, b3, b4);
    k_gemm2<<<dim3(LIN / 128, 4, BB), 256, g2_smem>>>();
    k_scan<<<(BB * DM) / 8, 256>>>(Dv, out);
}